// round 1
// baseline (speedup 1.0000x reference)
#include <cuda_runtime.h>
#include <math.h>

#define N_IMG 2
#define C_IN 48
#define H 192
#define W 192
#define HW (H*W)          // 36864
#define NHW (N_IMG*HW)    // 73728
#define DIM 128
#define HEADS 8
#define HEAD_DIM 16
#define PE_DIM 48
#define WIN 2
#define NVALS 4
#define SCALE 0.25f
#define TWO_PI 6.283185307179586f
#define EPS_F 1e-6f

// scratch (static device globals; no runtime allocation)
__device__ float g_off[NHW];
__device__ float g_yk[N_IMG * DIM * HW];   // [n][c][hw] channel-major
__device__ float g_yv[N_IMG * DIM * HW];
__device__ float g_pbk[NVALS * DIM];       // pb @ k_w + k_b
__device__ float g_pbv[NVALS * DIM];

// 1/dt for paired sin/cos frequencies: dt[2m] = 10000^(m/12) = 10^(m/3)
__constant__ float c_inv_dt[12] = {
    1.0f,
    0.46415888336127786f,
    0.21544346900318834f,
    0.1f,
    0.046415888336127774f,
    0.021544346900318832f,
    0.01f,
    0.0046415888336127786f,
    0.0021544346900318834f,
    0.001f,
    0.00046415888336127786f,
    0.00021544346900318834f
};

// ---------------------------------------------------------------------------
// K0: window-position-bias projected through k_w / v_w (constant per launch)
// ---------------------------------------------------------------------------
__global__ void pb_kernel(const float* __restrict__ kw, const float* __restrict__ kb,
                          const float* __restrict__ vw, const float* __restrict__ vb) {
    int o = threadIdx.x;  // 0..127
    #pragma unroll
    for (int j = 0; j < NVALS; j++) {
        float dy = (float)(j >> 1);
        float dx = (float)(j & 1);
        float yv_ = dy / (1.0f + EPS_F) * TWO_PI;
        float xv_ = dx / (1.0f + EPS_F) * TWO_PI;
        float acck = kb[o];
        float accv = vb[o];
        #pragma unroll
        for (int m = 0; m < 12; m++) {
            float sy, cy, sx, cx;
            sincosf(yv_ * c_inv_dt[m], &sy, &cy);
            sincosf(xv_ * c_inv_dt[m], &sx, &cx);
            acck += sy * kw[(2*m)*DIM + o]      + cy * kw[(2*m+1)*DIM + o]
                  + sx * kw[(24+2*m)*DIM + o]   + cx * kw[(25+2*m)*DIM + o];
            accv += sy * vw[(2*m)*DIM + o]      + cy * vw[(2*m+1)*DIM + o]
                  + sx * vw[(24+2*m)*DIM + o]   + cx * vw[(25+2*m)*DIM + o];
        }
        g_pbk[j*DIM + o] = acck;
        g_pbv[j*DIM + o] = accv;
    }
}

// ---------------------------------------------------------------------------
// K1: 3x3 conv over concat(y,x) (96 ch) -> 1 ch offset, scaled by 2/W
// ---------------------------------------------------------------------------
__global__ void conv_kernel(const float* __restrict__ y, const float* __restrict__ x,
                            const float* __restrict__ cw, const float* __restrict__ cb) {
    __shared__ float sw[96 * 9];
    int tid = threadIdx.y * 32 + threadIdx.x;
    for (int i = tid; i < 96 * 9; i += 256) sw[i] = cw[i];
    __syncthreads();

    int w0 = blockIdx.x * 32 + threadIdx.x;
    int h0 = blockIdx.y * 8 + threadIdx.y;
    int n  = blockIdx.z;

    const float* ybase = y + (size_t)n * C_IN * HW;
    const float* xbase = x + (size_t)n * C_IN * HW;

    float acc = cb[0];
    for (int ic = 0; ic < 96; ic++) {
        const float* src = (ic < 48) ? (ybase + ic * HW) : (xbase + (ic - 48) * HW);
        const float* wr = &sw[ic * 9];
        #pragma unroll
        for (int kh = 0; kh < 3; kh++) {
            int hh = h0 + kh - 1;
            if (hh < 0 || hh >= H) continue;
            const float* row = src + hh * W;
            #pragma unroll
            for (int kx = 0; kx < 3; kx++) {
                int ww = w0 + kx - 1;
                if (ww < 0 || ww >= W) continue;
                acc += row[ww] * wr[kh * 3 + kx];
            }
        }
    }
    g_off[n * HW + h0 * W + w0] = acc * (2.0f / (float)W);
}

// ---------------------------------------------------------------------------
// K2: yk = y @ k_w + k_b, yv = y @ v_w + v_b, stored channel-major [n][c][hw]
// ---------------------------------------------------------------------------
__global__ void __launch_bounds__(256) ykv_kernel(
        const float* __restrict__ y,
        const float* __restrict__ kw, const float* __restrict__ kb,
        const float* __restrict__ vw, const float* __restrict__ vb) {
    __shared__ float skw[PE_DIM * DIM];   // 24 KB
    __shared__ float svw[PE_DIM * DIM];   // 24 KB
    int tid = threadIdx.x;
    for (int i = tid; i < PE_DIM * DIM; i += 256) { skw[i] = kw[i]; svw[i] = vw[i]; }
    __syncthreads();

    int p  = blockIdx.x * 256 + tid;      // 288 * 256 = 73728, exact
    int n  = p / HW;
    int hw = p - n * HW;

    const float* yb = y + (size_t)n * C_IN * HW + hw;
    float yr[48];
    #pragma unroll
    for (int c = 0; c < 48; c++) yr[c] = yb[c * HW];

    float* ok = g_yk + (size_t)n * DIM * HW + hw;
    float* ov = g_yv + (size_t)n * DIM * HW + hw;

    for (int o0 = 0; o0 < DIM; o0 += 8) {
        float ak[8], av[8];
        #pragma unroll
        for (int i = 0; i < 8; i++) { ak[i] = kb[o0 + i]; av[i] = vb[o0 + i]; }
        #pragma unroll
        for (int c = 0; c < 48; c++) {
            float yc = yr[c];
            float4 k0 = *(const float4*)&skw[c * DIM + o0];
            float4 k1 = *(const float4*)&skw[c * DIM + o0 + 4];
            float4 v0 = *(const float4*)&svw[c * DIM + o0];
            float4 v1 = *(const float4*)&svw[c * DIM + o0 + 4];
            ak[0] += yc * k0.x; ak[1] += yc * k0.y; ak[2] += yc * k0.z; ak[3] += yc * k0.w;
            ak[4] += yc * k1.x; ak[5] += yc * k1.y; ak[6] += yc * k1.z; ak[7] += yc * k1.w;
            av[0] += yc * v0.x; av[1] += yc * v0.y; av[2] += yc * v0.z; av[3] += yc * v0.w;
            av[4] += yc * v1.x; av[5] += yc * v1.y; av[6] += yc * v1.z; av[7] += yc * v1.w;
        }
        #pragma unroll
        for (int i = 0; i < 8; i++) {
            ok[(o0 + i) * HW] = ak[i];
            ov[(o0 + i) * HW] = av[i];
        }
    }
}

// ---------------------------------------------------------------------------
// K3: q = (x + PE(frac)) @ q_w + q_b; 4-way window attention; NCHW output
// ---------------------------------------------------------------------------
__global__ void __launch_bounds__(128) attn_kernel(
        const float* __restrict__ x,
        const float* __restrict__ qw, const float* __restrict__ qb,
        float* __restrict__ out) {
    __shared__ float sqw[PE_DIM * DIM];   // 24 KB
    __shared__ float spbk[NVALS * DIM];
    __shared__ float spbv[NVALS * DIM];
    __shared__ float sqb[DIM];

    int tid = threadIdx.x;
    for (int i = tid; i < PE_DIM * DIM; i += 128) sqw[i] = qw[i];
    for (int i = tid; i < NVALS * DIM; i += 128) { spbk[i] = g_pbk[i]; spbv[i] = g_pbv[i]; }
    if (tid < DIM) sqb[tid] = qb[tid];
    __syncthreads();

    int p  = blockIdx.x * 128 + tid;      // 576 * 128 = 73728, exact
    int n  = p / HW;
    int hw = p - n * HW;
    int gh = hw / W;
    int gw = hw - gh * W;

    float off = g_off[p];
    float gx  = (float)gw + off;
    float x0f = floorf(gx);
    float fx  = gx - x0f;
    int   x0  = (int)x0f;

    // x_in = x + points-PE. y-frac is exactly 0 -> PE[0:24] = [0,1,0,1,...]
    const float* xb = x + (size_t)n * C_IN * HW + hw;
    float xin[48];
    #pragma unroll
    for (int c = 0; c < 24; c++) xin[c] = xb[c * HW] + ((c & 1) ? 1.0f : 0.0f);
    float xe = fx * (TWO_PI / ((float)WIN + EPS_F));
    #pragma unroll
    for (int m = 0; m < 12; m++) {
        float s, co;
        sincosf(xe * c_inv_dt[m], &s, &co);
        xin[24 + 2*m]     = xb[(24 + 2*m) * HW] + s;
        xin[24 + 2*m + 1] = xb[(24 + 2*m + 1) * HW] + co;
    }

    // sample linear indices (clamped 2x2 window)
    int lin[4];
    #pragma unroll
    for (int j = 0; j < 4; j++) {
        int iy = min(max(gh + (j >> 1), 0), H - 1);
        int ix = min(max(x0 + (j & 1),  0), W - 1);
        lin[j] = iy * W + ix;
    }

    const float* ykb = g_yk + (size_t)n * DIM * HW;
    const float* yvb = g_yv + (size_t)n * DIM * HW;
    float* outb = out + (size_t)n * DIM * HW + hw;

    #pragma unroll 1
    for (int h8 = 0; h8 < HEADS; h8++) {
        // q for this head
        float q[16];
        #pragma unroll
        for (int d = 0; d < 16; d++) q[d] = sqb[h8 * 16 + d];
        #pragma unroll
        for (int c = 0; c < 48; c++) {
            float xc = xin[c];
            const float* wr = &sqw[c * DIM + h8 * 16];
            #pragma unroll
            for (int d = 0; d < 16; d += 4) {
                float4 w4 = *(const float4*)&wr[d];
                q[d]   += xc * w4.x;
                q[d+1] += xc * w4.y;
                q[d+2] += xc * w4.z;
                q[d+3] += xc * w4.w;
            }
        }

        // scores
        float s[4];
        #pragma unroll
        for (int j = 0; j < 4; j++) {
            float acc = 0.0f;
            #pragma unroll
            for (int d = 0; d < 16; d++) {
                int c = h8 * 16 + d;
                float kv = ykb[c * HW + lin[j]] + spbk[j * DIM + c];
                acc += q[d] * kv;
            }
            s[j] = acc * SCALE;
        }

        // softmax over 4
        float mx = fmaxf(fmaxf(s[0], s[1]), fmaxf(s[2], s[3]));
        float e[4];
        float se = 0.0f;
        #pragma unroll
        for (int j = 0; j < 4; j++) { e[j] = expf(s[j] - mx); se += e[j]; }
        float inv = 1.0f / se;

        // output = sum_j a_j * v_j
        float o[16];
        #pragma unroll
        for (int d = 0; d < 16; d++) o[d] = 0.0f;
        #pragma unroll
        for (int j = 0; j < 4; j++) {
            float aj = e[j] * inv;
            #pragma unroll
            for (int d = 0; d < 16; d++) {
                int c = h8 * 16 + d;
                float vv = yvb[c * HW + lin[j]] + spbv[j * DIM + c];
                o[d] += aj * vv;
            }
        }
        #pragma unroll
        for (int d = 0; d < 16; d++) outb[(h8 * 16 + d) * HW] = o[d];
    }
}

// ---------------------------------------------------------------------------
extern "C" void kernel_launch(void* const* d_in, const int* in_sizes, int n_in,
                              void* d_out, int out_size) {
    const float* y      = (const float*)d_in[0];
    const float* x      = (const float*)d_in[1];
    const float* conv_w = (const float*)d_in[2];
    const float* conv_b = (const float*)d_in[3];
    const float* q_w    = (const float*)d_in[4];
    const float* q_b    = (const float*)d_in[5];
    const float* k_w    = (const float*)d_in[6];
    const float* k_b    = (const float*)d_in[7];
    const float* v_w    = (const float*)d_in[8];
    const float* v_b    = (const float*)d_in[9];
    float* out = (float*)d_out;

    pb_kernel<<<1, 128>>>(k_w, k_b, v_w, v_b);

    dim3 cgrid(W / 32, H / 8, N_IMG);
    dim3 cblk(32, 8);
    conv_kernel<<<cgrid, cblk>>>(y, x, conv_w, conv_b);

    ykv_kernel<<<NHW / 256, 256>>>(y, k_w, k_b, v_w, v_b);

    attn_kernel<<<NHW / 128, 128>>>(x, q_w, q_b, out);
}

// round 5
// speedup vs baseline: 1.1390x; 1.1390x over previous
#include <cuda_runtime.h>
#include <math.h>

#define N_IMG 2
#define C_IN 48
#define H 192
#define W 192
#define HW (H*W)          // 36864
#define NHW (N_IMG*HW)    // 73728
#define DIM 128
#define HEADS 8
#define PE_DIM 48
#define SCALE 0.25f
#define TWO_PI 6.283185307179586f
#define EPS_F 1e-6f

// scratch
__device__ float g_kv[(size_t)NHW * 256];   // [p][256]: 0:128 = k, 128:256 = v
__device__ float g_q [(size_t)NHW * 128];   // [p][128]
__device__ float g_pe[24 * NHW];            // [k][p] channel-major PE of frac_x
__device__ int   g_x0[NHW];
__device__ float g_pbk[4 * DIM];            // pb @ k_w  (no bias)
__device__ float g_pbv[4 * DIM];            // pb @ v_w

__constant__ float c_inv_dt[12] = {
    1.0f, 0.46415888336127786f, 0.21544346900318834f, 0.1f,
    0.046415888336127774f, 0.021544346900318832f, 0.01f,
    0.0046415888336127786f, 0.0021544346900318834f, 0.001f,
    0.00046415888336127786f, 0.00021544346900318834f
};

typedef unsigned long long ull;
__device__ __forceinline__ ull pk2(float x, float y) {
    ull r; asm("mov.b64 %0,{%1,%2};" : "=l"(r) : "f"(x), "f"(y)); return r;
}
__device__ __forceinline__ ull ffma2(ull a, ull b, ull c) {
    ull d; asm("fma.rn.f32x2 %0,%1,%2,%3;" : "=l"(d) : "l"(a), "l"(b), "l"(c)); return d;
}
__device__ __forceinline__ float2 upk(ull a) {
    float2 r; asm("mov.b64 {%0,%1},%2;" : "=f"(r.x), "=f"(r.y) : "l"(a)); return r;
}

// ---------------------------------------------------------------------------
// K0: window-position-bias projected through k_w / v_w (NO bias; GEMM adds it)
// ---------------------------------------------------------------------------
__global__ void pb_kernel(const float* __restrict__ kw, const float* __restrict__ vw) {
    int o = threadIdx.x;  // 0..127
    #pragma unroll
    for (int j = 0; j < 4; j++) {
        float dy = (float)(j >> 1);
        float dx = (float)(j & 1);
        float yv_ = dy / (1.0f + EPS_F) * TWO_PI;
        float xv_ = dx / (1.0f + EPS_F) * TWO_PI;
        float acck = 0.0f, accv = 0.0f;
        #pragma unroll
        for (int m = 0; m < 12; m++) {
            float sy, cy, sx, cx;
            sincosf(yv_ * c_inv_dt[m], &sy, &cy);
            sincosf(xv_ * c_inv_dt[m], &sx, &cx);
            acck += sy * kw[(2*m)*DIM + o]    + cy * kw[(2*m+1)*DIM + o]
                  + sx * kw[(24+2*m)*DIM + o] + cx * kw[(25+2*m)*DIM + o];
            accv += sy * vw[(2*m)*DIM + o]    + cy * vw[(2*m+1)*DIM + o]
                  + sx * vw[(24+2*m)*DIM + o] + cx * vw[(25+2*m)*DIM + o];
        }
        g_pbk[j*DIM + o] = acck;
        g_pbv[j*DIM + o] = accv;
    }
}

// ---------------------------------------------------------------------------
// K1: 3x3 conv (96ch -> 1) => offset; also writes floor index + PE(frac_x)
// ---------------------------------------------------------------------------
__global__ void conv_kernel(const float* __restrict__ y, const float* __restrict__ x,
                            const float* __restrict__ cw, const float* __restrict__ cb) {
    __shared__ float sw[96 * 9];
    int tid = threadIdx.y * 32 + threadIdx.x;
    for (int i = tid; i < 96 * 9; i += 256) sw[i] = cw[i];
    __syncthreads();

    int w0 = blockIdx.x * 32 + threadIdx.x;
    int h0 = blockIdx.y * 8 + threadIdx.y;
    int n  = blockIdx.z;

    const float* ybase = y + (size_t)n * C_IN * HW;
    const float* xbase = x + (size_t)n * C_IN * HW;

    float acc = cb[0];
    for (int ic = 0; ic < 96; ic++) {
        const float* src = (ic < 48) ? (ybase + ic * HW) : (xbase + (ic - 48) * HW);
        const float* wr = &sw[ic * 9];
        #pragma unroll
        for (int kh = 0; kh < 3; kh++) {
            int hh = h0 + kh - 1;
            if (hh < 0 || hh >= H) continue;
            const float* row = src + hh * W;
            #pragma unroll
            for (int kx = 0; kx < 3; kx++) {
                int ww = w0 + kx - 1;
                if (ww < 0 || ww >= W) continue;
                acc += row[ww] * wr[kh * 3 + kx];
            }
        }
    }
    float offv = acc * (2.0f / (float)W);
    float gx = (float)w0 + offv;
    float fl = floorf(gx);
    int p = n * HW + h0 * W + w0;
    g_x0[p] = (int)fl;
    float xe = (gx - fl) * (TWO_PI / (2.0f + EPS_F));
    #pragma unroll
    for (int m = 0; m < 12; m++) {
        float s, c;
        sincosf(xe * c_inv_dt[m], &s, &c);
        g_pe[(2*m)   * NHW + p] = s;
        g_pe[(2*m+1) * NHW + p] = c;
    }
}

// ---------------------------------------------------------------------------
// K2: fused tiled GEMM. grid.y in [0,6):
//   0..3 : C = y   @ [kw | vw]  -> g_kv[p][256]   (by*64 column tile)
//   4..5 : C = xin @ qw         -> g_q [p][128]   ((by-4)*64 column tile)
// BM=128, BN=64, K=48, 256 threads, 8x4 microtile, packed f32x2 FMA.
// ---------------------------------------------------------------------------
__global__ void __launch_bounds__(256) gemm_kernel(
        const float* __restrict__ y, const float* __restrict__ x,
        const float* __restrict__ qw, const float* __restrict__ qb,
        const float* __restrict__ kw, const float* __restrict__ kb,
        const float* __restrict__ vw, const float* __restrict__ vb) {
    __shared__ float As[48][128];
    __shared__ float Bs[48][64];

    int tid = threadIdx.x;
    int bx = blockIdx.x, by = blockIdx.y;
    int p0 = bx * 128;
    int n = p0 / HW;
    int hw0 = p0 - n * HW;
    bool isQ = (by >= 4);

    // ---- load A tile [48][128] ----
    {
        int i = tid & 127;
        int chalf = tid >> 7;  // 0 or 1
        if (!isQ) {
            const float* yb = y + (size_t)n * C_IN * HW + hw0 + i;
            #pragma unroll
            for (int c = chalf; c < 48; c += 2) As[c][i] = yb[(size_t)c * HW];
        } else {
            const float* xb = x + (size_t)n * C_IN * HW + hw0 + i;
            int p = p0 + i;
            #pragma unroll
            for (int c = chalf; c < 48; c += 2) {
                float v = xb[(size_t)c * HW];
                if (c < 24) v += (float)(c & 1);
                else        v += g_pe[(c - 24) * NHW + p];
                As[c][i] = v;
            }
        }
    }

    // ---- load B tile [48][64] ----
    const float* Wm; const float* bias; int og;
    if (isQ) { Wm = qw; bias = qb; og = (by - 4) * 64; }
    else {
        int o = by * 64;
        if (o < 128) { Wm = kw; bias = kb; og = o; }
        else         { Wm = vw; bias = vb; og = o - 128; }
    }
    #pragma unroll
    for (int kk = 0; kk < 12; kk++) {
        int idx = tid + kk * 256;
        int c = idx >> 6, o = idx & 63;
        Bs[c][o] = Wm[c * DIM + og + o];
    }
    __syncthreads();

    int tx = tid & 15, ty = tid >> 4;
    int otx = tx * 4, pr0 = ty * 8;

    ull acc[4][4];
    float4 bb = *(const float4*)&bias[og + otx];
    #pragma unroll
    for (int pp = 0; pp < 4; pp++) {
        acc[pp][0] = pk2(bb.x, bb.x);
        acc[pp][1] = pk2(bb.y, bb.y);
        acc[pp][2] = pk2(bb.z, bb.z);
        acc[pp][3] = pk2(bb.w, bb.w);
    }

    #pragma unroll
    for (int c = 0; c < 48; c++) {
        ull a0 = *(const ull*)&As[c][pr0];
        ull a1 = *(const ull*)&As[c][pr0 + 2];
        ull a2 = *(const ull*)&As[c][pr0 + 4];
        ull a3 = *(const ull*)&As[c][pr0 + 6];
        float4 b4 = *(const float4*)&Bs[c][otx];
        ull b0 = pk2(b4.x, b4.x), b1 = pk2(b4.y, b4.y);
        ull b2 = pk2(b4.z, b4.z), b3 = pk2(b4.w, b4.w);
        acc[0][0] = ffma2(a0, b0, acc[0][0]); acc[0][1] = ffma2(a0, b1, acc[0][1]);
        acc[0][2] = ffma2(a0, b2, acc[0][2]); acc[0][3] = ffma2(a0, b3, acc[0][3]);
        acc[1][0] = ffma2(a1, b0, acc[1][0]); acc[1][1] = ffma2(a1, b1, acc[1][1]);
        acc[1][2] = ffma2(a1, b2, acc[1][2]); acc[1][3] = ffma2(a1, b3, acc[1][3]);
        acc[2][0] = ffma2(a2, b0, acc[2][0]); acc[2][1] = ffma2(a2, b1, acc[2][1]);
        acc[2][2] = ffma2(a2, b2, acc[2][2]); acc[2][3] = ffma2(a2, b3, acc[2][3]);
        acc[3][0] = ffma2(a3, b0, acc[3][0]); acc[3][1] = ffma2(a3, b1, acc[3][1]);
        acc[3][2] = ffma2(a3, b2, acc[3][2]); acc[3][3] = ffma2(a3, b3, acc[3][3]);
    }

    float* C; int ld; int ocol;
    if (isQ) { C = g_q + (size_t)p0 * 128; ld = 128; ocol = og + otx; }
    else     { C = g_kv + (size_t)p0 * 256; ld = 256; ocol = by * 64 + otx; }
    #pragma unroll
    for (int pp = 0; pp < 4; pp++) {
        float2 c0 = upk(acc[pp][0]), c1 = upk(acc[pp][1]);
        float2 c2 = upk(acc[pp][2]), c3 = upk(acc[pp][3]);
        int pr = pr0 + 2 * pp;
        float4 ev = make_float4(c0.x, c1.x, c2.x, c3.x);
        float4 od = make_float4(c0.y, c1.y, c2.y, c3.y);
        *(float4*)&C[(size_t)pr * ld + ocol] = ev;
        *(float4*)&C[(size_t)(pr + 1) * ld + ocol] = od;
    }
}

// ---------------------------------------------------------------------------
// K3: warp-per-pixel attention. 512 threads = 16 warps = 16 pixels per block.
// lane <-> channel (c = lane + 32*i), 16-lane shuffle reduction per head.
// smem transpose for coalesced NCHW output.
// ---------------------------------------------------------------------------
__global__ void __launch_bounds__(512) attn_kernel(float* __restrict__ out) {
    __shared__ float spbk[4][128];
    __shared__ float spbv[4][128];
    __shared__ float sout[128][17];   // pad to kill bank conflicts

    int tid = threadIdx.x;
    spbk[tid >> 7][tid & 127] = g_pbk[tid];
    spbv[tid >> 7][tid & 127] = g_pbv[tid];
    __syncthreads();

    int w  = tid >> 5;
    int lane = tid & 31;
    int p = blockIdx.x * 16 + w;
    int n = p / HW;
    int hw = p - n * HW;
    int gh = hw / W;
    int x0 = g_x0[p];

    int lin[4];
    #pragma unroll
    for (int j = 0; j < 4; j++) {
        int iy = min(max(gh + (j >> 1), 0), H - 1);
        int ix = min(max(x0 + (j & 1),  0), W - 1);
        lin[j] = n * HW + iy * W + ix;
    }

    const float* qrow = g_q + (size_t)p * 128;

    #pragma unroll
    for (int i = 0; i < 4; i++) {
        int c = lane + 32 * i;
        float qv = qrow[c] * SCALE;
        float kj[4], vj[4], s[4];
        #pragma unroll
        for (int j = 0; j < 4; j++) {
            const float* r = g_kv + (size_t)lin[j] * 256;
            kj[j] = r[c]       + spbk[j][c];
            vj[j] = r[128 + c] + spbv[j][c];
            float part = qv * kj[j];
            part += __shfl_xor_sync(0xffffffffu, part, 8);
            part += __shfl_xor_sync(0xffffffffu, part, 4);
            part += __shfl_xor_sync(0xffffffffu, part, 2);
            part += __shfl_xor_sync(0xffffffffu, part, 1);
            s[j] = part;
        }
        float mx = fmaxf(fmaxf(s[0], s[1]), fmaxf(s[2], s[3]));
        float e0 = __expf(s[0] - mx), e1 = __expf(s[1] - mx);
        float e2 = __expf(s[2] - mx), e3 = __expf(s[3] - mx);
        float inv = 1.0f / (e0 + e1 + e2 + e3);
        float oo = (e0 * vj[0] + e1 * vj[1] + e2 * vj[2] + e3 * vj[3]) * inv;
        sout[c][w] = oo;
    }
    __syncthreads();

    // coalesced NCHW write: block covers 16 consecutive hw in one image
    int p0 = blockIdx.x * 16;
    int n0 = p0 / HW;
    int hw0 = p0 - n0 * HW;
    int ch = tid >> 2;
    int px = (tid & 3) * 4;
    float4 v = make_float4(sout[ch][px], sout[ch][px + 1], sout[ch][px + 2], sout[ch][px + 3]);
    *(float4*)&out[(size_t)n0 * DIM * HW + (size_t)ch * HW + hw0 + px] = v;
}

// ---------------------------------------------------------------------------
extern "C" void kernel_launch(void* const* d_in, const int* in_sizes, int n_in,
                              void* d_out, int out_size) {
    const float* y      = (const float*)d_in[0];
    const float* x      = (const float*)d_in[1];
    const float* conv_w = (const float*)d_in[2];
    const float* conv_b = (const float*)d_in[3];
    const float* q_w    = (const float*)d_in[4];
    const float* q_b    = (const float*)d_in[5];
    const float* k_w    = (const float*)d_in[6];
    const float* k_b    = (const float*)d_in[7];
    const float* v_w    = (const float*)d_in[8];
    const float* v_b    = (const float*)d_in[9];
    float* out = (float*)d_out;

    pb_kernel<<<1, 128>>>(k_w, v_w);

    dim3 cgrid(W / 32, H / 8, N_IMG);
    dim3 cblk(32, 8);
    conv_kernel<<<cgrid, cblk>>>(y, x, conv_w, conv_b);

    dim3 ggrid(NHW / 128, 6);
    gemm_kernel<<<ggrid, 256>>>(y, x, q_w, q_b, k_w, k_b, v_w, v_b);

    attn_kernel<<<NHW / 16, 512>>>(out);
}